// round 9
// baseline (speedup 1.0000x reference)
#include <cuda_runtime.h>
#include <cuda_fp16.h>
#include <cstdint>

// ===================== problem constants =====================
#define NNF 128
#define NEF 64
#define NGF 64
#define HID 128
#define TGT 64

#define THREADS 448
#define NWARPS  14
#define GRID_X  152

#define KT1 24   // 384/16 k-tiles, GEMM1
#define NT1 16   // 128/8  n-tiles, GEMM1 (8 per phase)
#define KT2 8    // 128/16 k-tiles, GEMM2
#define NT2 8    // 64/8   n-tiles, GEMM2

// ===================== smem offsets (bytes) =====================
#define S_W1  0u        // 24 kt x 8 pairs x 32 lanes x 16B = 98304
#define S_W2  98304u    // 8 kt x 4 pairs x 32 x 16B = 16384
#define S_B1  114688u   // 512
#define S_B2  115200u   // 256
#define S_H   115456u   // 14 warps x 8192
#define S_TOTAL (S_H + NWARPS * 8192u)   // 230144

// ===================== helpers =====================
__device__ __forceinline__ uint32_t pack2h(float lo, float hi) {
    uint32_t r;
    asm("cvt.rn.f16x2.f32 %0, %1, %2;" : "=r"(r) : "f"(hi), "f"(lo));
    return r;
}
// D += A * B  (m16n8k16, fp16 in, f32 accum)
__device__ __forceinline__ void mma_f16(float* c, const uint32_t* a, uint32_t b0, uint32_t b1) {
    asm volatile("mma.sync.aligned.m16n8k16.row.col.f32.f16.f16.f32 "
        "{%0,%1,%2,%3}, {%4,%5,%6,%7}, {%8,%9}, {%0,%1,%2,%3};"
        : "+f"(c[0]), "+f"(c[1]), "+f"(c[2]), "+f"(c[3])
        : "r"(a[0]), "r"(a[1]), "r"(a[2]), "r"(a[3]), "r"(b0), "r"(b1));
}
__device__ __forceinline__ void load8(float2* v, const float* p0, const float* p1,
                                      const float* p2, const float* p3) {
    v[0] = *(const float2*)p0; v[1] = *(const float2*)(p0 + 8);
    v[2] = *(const float2*)p1; v[3] = *(const float2*)(p1 + 8);
    v[4] = *(const float2*)p2; v[5] = *(const float2*)(p2 + 8);
    v[6] = *(const float2*)p3; v[7] = *(const float2*)(p3 + 8);
}
__device__ __forceinline__ void cvt8(uint32_t* af, const float2* v) {
    af[0] = pack2h(v[0].x, v[0].y);  // (r00, c0)
    af[1] = pack2h(v[2].x, v[2].y);  // (r01, c0)
    af[2] = pack2h(v[1].x, v[1].y);  // (r00, c0+8)
    af[3] = pack2h(v[3].x, v[3].y);  // (r01, c0+8)
    af[4] = pack2h(v[4].x, v[4].y);  // (r10, c0)
    af[5] = pack2h(v[6].x, v[6].y);  // (r11, c0)
    af[6] = pack2h(v[5].x, v[5].y);  // (r10, c0+8)
    af[7] = pack2h(v[7].x, v[7].y);  // (r11, c0+8)
}

// ===================== device scratch (uint4-paired fragments) =====================
__device__ __align__(16) uint2 g_w1[KT1 * NT1 * 32];   // interleaved pair layout
__device__ __align__(16) uint2 g_w2[KT2 * NT2 * 32];
__device__ unsigned int g_counter;

// W1 [384,128], W2 [128,64] ([k][n] row-major) -> per-lane m16n8k16 B fragments,
// paired: uint4 entry ((kt*8+np)*32+lane) = {frag(nt=2np), frag(nt=2np+1)}.
// frag(kt,nt,lane) = { {W[k0][n],W[k0+1][n]}, {W[k0+8][n],W[k0+9][n]} },
// k0 = kt*16+(lane&3)*2, n = nt*8+(lane>>2).
__global__ void prep_kernel(const float* __restrict__ W1, const float* __restrict__ W2) {
    int idx = blockIdx.x * blockDim.x + threadIdx.x;
    if (idx == 0) g_counter = 0u;
    const int total1 = KT1 * NT1 * 32;
    if (idx < total1) {
        int lane = idx & 31, tile = idx >> 5;
        int nt = tile % NT1, kt = tile / NT1;
        int k0 = kt * 16 + (lane & 3) * 2;
        int n  = nt * 8 + (lane >> 2);
        float w00 = W1[(size_t)k0 * HID + n];
        float w01 = W1[(size_t)(k0 + 1) * HID + n];
        float w10 = W1[(size_t)(k0 + 8) * HID + n];
        float w11 = W1[(size_t)(k0 + 9) * HID + n];
        size_t dst = (size_t)2 * (((size_t)kt * 8 + (nt >> 1)) * 32 + lane) + (nt & 1);
        g_w1[dst] = make_uint2(pack2h(w00, w01), pack2h(w10, w11));
    } else if (idx < total1 + KT2 * NT2 * 32) {
        int j = idx - total1;
        int lane = j & 31, tile = j >> 5;
        int nt = tile % NT2, kt = tile / NT2;
        int k0 = kt * 16 + (lane & 3) * 2;
        int n  = nt * 8 + (lane >> 2);
        float w00 = W2[(size_t)k0 * TGT + n];
        float w01 = W2[(size_t)(k0 + 1) * TGT + n];
        float w10 = W2[(size_t)(k0 + 8) * TGT + n];
        float w11 = W2[(size_t)(k0 + 9) * TGT + n];
        size_t dst = (size_t)2 * (((size_t)kt * 4 + (nt >> 1)) * 32 + lane) + (nt & 1);
        g_w2[dst] = make_uint2(pack2h(w00, w01), pack2h(w10, w11));
    }
}

// ===================== main fused kernel =====================
extern "C" __global__ void __launch_bounds__(THREADS, 1)
edge_mlp(const float* __restrict__ ek, const float* __restrict__ vrk,
         const float* __restrict__ vsk, const float* __restrict__ u,
         const int* __restrict__ batch,
         const float* __restrict__ b1, const float* __restrict__ b2,
         float* __restrict__ out, int ngroups) {
    extern __shared__ __align__(16) unsigned char smem[];
    const int tid = threadIdx.x;

    // -------- prologue: weight fragments + biases to smem --------
    {
        uint4* d = (uint4*)(smem + S_W1);
        const uint4* s = (const uint4*)g_w1;
        for (int i = tid; i < 98304 / 16; i += THREADS) d[i] = s[i];
        d = (uint4*)(smem + S_W2); s = (const uint4*)g_w2;
        for (int i = tid; i < 16384 / 16; i += THREADS) d[i] = s[i];
        float* b1s = (float*)(smem + S_B1);
        float* b2s = (float*)(smem + S_B2);
        if (tid < HID) b1s[tid] = b1[tid];
        if (tid < TGT) b2s[tid] = b2[tid];
    }
    __syncthreads();

    const uint4* w1p = (const uint4*)(smem + S_W1);
    const uint4* w2p = (const uint4*)(smem + S_W2);
    const float* b1s = (const float*)(smem + S_B1);
    const float* b2s = (const float*)(smem + S_B2);

    const int lane = tid & 31;
    const int wid  = tid >> 5;
    const int qrow = lane >> 2;        // 0..7
    const int qcol = (lane & 3) * 2;   // 0,2,4,6

    uint4* hbuf = (uint4*)(smem + S_H + (size_t)wid * 8192u);

    unsigned int cur = 0xFFFFFFFFu;
    if (lane == 0) cur = atomicAdd(&g_counter, 1u);
    cur = __shfl_sync(0xFFFFFFFFu, cur, 0);

    while (cur < (unsigned)ngroups) {
        unsigned int nxt = 0xFFFFFFFFu;
        if (lane == 0) nxt = atomicAdd(&g_counter, 1u);

        const int rbase = (int)cur * 32;
        const int r00 = rbase + qrow,      r01 = r00 + 8;
        const int r10 = rbase + 16 + qrow, r11 = r10 + 8;
        const int g00 = batch[r00], g01 = batch[r01];
        const int g10 = batch[r10], g11 = batch[r11];

        // ============ GEMM1 in two N-phases (hidden cols ph*64..ph*64+63) ============
        #pragma unroll 1
        for (int ph = 0; ph < 2; ++ph) {
            const int ph4 = ph * 4;
            float acc[64];   // [rb(2)][ntlocal(8)][4]
            #pragma unroll
            for (int i = 0; i < 64; ++i) acc[i] = 0.f;

            float2 v[8];
            uint32_t af[8];
            const float *q0, *q1, *q2, *q3;

            #define MMABLK(KT) do {                                               \
                const uint4* _bw = w1p + ((size_t)(KT) * 8 + ph4) * 32 + lane;    \
                _Pragma("unroll")                                                 \
                for (int np = 0; np < 4; ++np) {                                  \
                    const uint4 f = _bw[np * 32];                                 \
                    mma_f16(acc + (np * 2) * 4,          af,     f.x, f.y);       \
                    mma_f16(acc + 32 + (np * 2) * 4,     af + 4, f.x, f.y);       \
                    mma_f16(acc + (np * 2 + 1) * 4,      af,     f.z, f.w);       \
                    mma_f16(acc + 32 + (np * 2 + 1) * 4, af + 4, f.z, f.w);       \
                }                                                                 \
            } while (0)

            #define SET_EK  q0 = ek  + (size_t)r00 * NEF + qcol; q1 = ek  + (size_t)r01 * NEF + qcol; \
                            q2 = ek  + (size_t)r10 * NEF + qcol; q3 = ek  + (size_t)r11 * NEF + qcol
            #define SET_VRK q0 = vrk + (size_t)r00 * NNF + qcol; q1 = vrk + (size_t)r01 * NNF + qcol; \
                            q2 = vrk + (size_t)r10 * NNF + qcol; q3 = vrk + (size_t)r11 * NNF + qcol
            #define SET_VSK q0 = vsk + (size_t)r00 * NNF + qcol; q1 = vsk + (size_t)r01 * NNF + qcol; \
                            q2 = vsk + (size_t)r10 * NNF + qcol; q3 = vsk + (size_t)r11 * NNF + qcol
            #define SET_U   q0 = u   + (size_t)g00 * NGF + qcol; q1 = u   + (size_t)g01 * NGF + qcol; \
                            q2 = u   + (size_t)g10 * NGF + qcol; q3 = u   + (size_t)g11 * NGF + qcol

            // seg(NT tiles): pipeline cvt(current) -> load(next) -> MMA(current)
            #define SEG(KT0, NT, NEXTSET) do {                                    \
                _Pragma("unroll")                                                 \
                for (int i = 0; i < (NT); ++i) {                                  \
                    cvt8(af, v);                                                  \
                    if (i + 1 < (NT)) {                                           \
                        load8(v, q0 + 16 * (i + 1), q1 + 16 * (i + 1),            \
                                 q2 + 16 * (i + 1), q3 + 16 * (i + 1));           \
                    } else { NEXTSET; }                                           \
                    MMABLK((KT0) + i);                                            \
                }                                                                 \
            } while (0)

            SET_EK;
            load8(v, q0, q1, q2, q3);
            SEG(0, 4,  { SET_VRK; load8(v, q0, q1, q2, q3); });
            SEG(4, 8,  { SET_VSK; load8(v, q0, q1, q2, q3); });
            SEG(12, 8, { SET_U;   load8(v, q0, q1, q2, q3); });
            SEG(20, 4, { });

            #undef SEG
            #undef SET_EK
            #undef SET_VRK
            #undef SET_VSK
            #undef SET_U
            #undef MMABLK

            // ---- bias + ReLU ----
            #pragma unroll
            for (int nt = 0; nt < 8; ++nt) {
                const float2 bb = *(const float2*)(b1s + ph * 64 + nt * 8 + qcol);
                #pragma unroll
                for (int rb = 0; rb < 2; ++rb) {
                    float* a = acc + rb * 32 + nt * 4;
                    a[0] = fmaxf(a[0] + bb.x, 0.f);
                    a[1] = fmaxf(a[1] + bb.y, 0.f);
                    a[2] = fmaxf(a[2] + bb.x, 0.f);
                    a[3] = fmaxf(a[3] + bb.y, 0.f);
                }
            }
            // ---- pack + spill h (A-frag layout for GEMM2) ----
            #pragma unroll
            for (int j = 0; j < 4; ++j) {
                const int kk = ph4 + j;
                #pragma unroll
                for (int rb = 0; rb < 2; ++rb) {
                    const float* s = acc + rb * 32 + j * 8;
                    uint4 q;
                    q.x = pack2h(s[0], s[1]);
                    q.y = pack2h(s[2], s[3]);
                    q.z = pack2h(s[4], s[5]);
                    q.w = pack2h(s[6], s[7]);
                    hbuf[(kk * 2 + rb) * 32 + lane] = q;
                }
            }
        }

        // ================= GEMM2: h (smem) @ W2 =================
        float c2[64];
        #pragma unroll
        for (int i = 0; i < 64; ++i) c2[i] = 0.f;

        #pragma unroll 1
        for (int kk = 0; kk < KT2; ++kk) {
            uint4 A0 = hbuf[(kk * 2 + 0) * 32 + lane];
            uint4 A1 = hbuf[(kk * 2 + 1) * 32 + lane];
            const uint32_t* a0 = (const uint32_t*)&A0;
            const uint32_t* a1 = (const uint32_t*)&A1;
            const uint4* bw = w2p + (size_t)kk * 4 * 32 + lane;
            #pragma unroll
            for (int np = 0; np < 4; ++np) {
                const uint4 f = bw[np * 32];
                mma_f16(c2 + (np * 2) * 4,          a0, f.x, f.y);
                mma_f16(c2 + 32 + (np * 2) * 4,     a1, f.x, f.y);
                mma_f16(c2 + (np * 2 + 1) * 4,      a0, f.z, f.w);
                mma_f16(c2 + 32 + (np * 2 + 1) * 4, a1, f.z, f.w);
            }
        }

        // ================= epilogue: + b2, store fp32 =================
        #pragma unroll
        for (int nt = 0; nt < 8; ++nt) {
            const float2 bb = *(const float2*)(b2s + nt * 8 + qcol);
            {
                const float* c = c2 + nt * 4;
                float2 o0, o1;
                o0.x = c[0] + bb.x; o0.y = c[1] + bb.y;
                o1.x = c[2] + bb.x; o1.y = c[3] + bb.y;
                *(float2*)(out + (size_t)r00 * TGT + nt * 8 + qcol) = o0;
                *(float2*)(out + (size_t)r01 * TGT + nt * 8 + qcol) = o1;
            }
            {
                const float* c = c2 + 32 + nt * 4;
                float2 o0, o1;
                o0.x = c[0] + bb.x; o0.y = c[1] + bb.y;
                o1.x = c[2] + bb.x; o1.y = c[3] + bb.y;
                *(float2*)(out + (size_t)r10 * TGT + nt * 8 + qcol) = o0;
                *(float2*)(out + (size_t)r11 * TGT + nt * 8 + qcol) = o1;
            }
        }

        cur = __shfl_sync(0xFFFFFFFFu, nxt, 0);
    }
}

// ===================== launch =====================
extern "C" void kernel_launch(void* const* d_in, const int* in_sizes, int n_in,
                              void* d_out, int out_size) {
    (void)n_in; (void)out_size;
    const float* ek  = (const float*)d_in[0];
    const float* vrk = (const float*)d_in[1];
    const float* vsk = (const float*)d_in[2];
    const float* u   = (const float*)d_in[3];
    const int*   batch = (const int*)d_in[4];
    const float* W1  = (const float*)d_in[5];
    const float* b1  = (const float*)d_in[6];
    const float* W2  = (const float*)d_in[7];
    const float* b2  = (const float*)d_in[8];
    float* out = (float*)d_out;

    const int E = in_sizes[0] / NEF;
    const int ngroups = E / 32;

    const int prep_total = KT1 * NT1 * 32 + KT2 * NT2 * 32;
    prep_kernel<<<(prep_total + 255) / 256, 256>>>(W1, W2);

    cudaFuncSetAttribute(edge_mlp, cudaFuncAttributeMaxDynamicSharedMemorySize, S_TOTAL);
    edge_mlp<<<GRID_X, THREADS, S_TOTAL>>>(ek, vrk, vsk, u, batch, b1, b2, out, ngroups);
}

// round 10
// speedup vs baseline: 1.1884x; 1.1884x over previous
#include <cuda_runtime.h>
#include <cuda_fp16.h>
#include <cstdint>

// ===================== problem constants =====================
#define NNF 128
#define NEF 64
#define NGF 64
#define HID 128
#define TGT 64

#define THREADS 384
#define NWARPS  12
#define GRID_X  152

#define KT1 24   // 384/16 k-tiles, GEMM1
#define NT1 16   // 128/8  n-tiles, GEMM1 (8 per phase)
#define KT2 8    // 128/16 k-tiles, GEMM2

// ===================== smem offsets (bytes) =====================
#define S_W1  0u        // 24 kt x 8 pairs x 32 lanes x 16B = 98304
#define S_W2  98304u    // 8 kt x 4 pairs x 32 x 16B = 16384
#define S_B1  114688u   // 512
#define S_B2  115200u   // 256
#define S_H   115456u   // 12 warps x 8192
#define S_TOTAL (S_H + NWARPS * 8192u)   // 213760

// ===================== helpers =====================
__device__ __forceinline__ uint32_t pack2h(float lo, float hi) {
    uint32_t r;
    asm("cvt.rn.f16x2.f32 %0, %1, %2;" : "=r"(r) : "f"(hi), "f"(lo));
    return r;
}
// D += A * B  (m16n8k16, fp16 in, f32 accum)
__device__ __forceinline__ void mma_f16(float* c, const uint32_t* a, uint32_t b0, uint32_t b1) {
    asm volatile("mma.sync.aligned.m16n8k16.row.col.f32.f16.f16.f32 "
        "{%0,%1,%2,%3}, {%4,%5,%6,%7}, {%8,%9}, {%0,%1,%2,%3};"
        : "+f"(c[0]), "+f"(c[1]), "+f"(c[2]), "+f"(c[3])
        : "r"(a[0]), "r"(a[1]), "r"(a[2]), "r"(a[3]), "r"(b0), "r"(b1));
}
__device__ __forceinline__ void load8(float2* v, const float* p0, const float* p1,
                                      const float* p2, const float* p3) {
    v[0] = *(const float2*)p0; v[1] = *(const float2*)(p0 + 8);
    v[2] = *(const float2*)p1; v[3] = *(const float2*)(p1 + 8);
    v[4] = *(const float2*)p2; v[5] = *(const float2*)(p2 + 8);
    v[6] = *(const float2*)p3; v[7] = *(const float2*)(p3 + 8);
}
__device__ __forceinline__ void cvt8(uint32_t* af, const float2* v) {
    af[0] = pack2h(v[0].x, v[0].y);  // (r00, c0)   A-frag row block 0
    af[1] = pack2h(v[2].x, v[2].y);  // (r01, c0)
    af[2] = pack2h(v[1].x, v[1].y);  // (r00, c0+8)
    af[3] = pack2h(v[3].x, v[3].y);  // (r01, c0+8)
    af[4] = pack2h(v[4].x, v[4].y);  // (r10, c0)   A-frag row block 1
    af[5] = pack2h(v[6].x, v[6].y);  // (r11, c0)
    af[6] = pack2h(v[5].x, v[5].y);  // (r10, c0+8)
    af[7] = pack2h(v[7].x, v[7].y);  // (r11, c0+8)
}

// ===================== device scratch (uint4-paired fragments) =====================
__device__ __align__(16) uint2 g_w1[KT1 * NT1 * 32];   // pair-interleaved layout
__device__ __align__(16) uint2 g_w2[KT2 * 8 * 32];
__device__ unsigned int g_counter;

// W1 [384,128], W2 [128,64] ([k][n] row-major) -> per-lane m16n8k16 B fragments,
// paired: uint4 entry ((kt*8+np)*32+lane) = {frag(nt=2np), frag(nt=2np+1)}.
// frag(kt,nt,lane) = { {W[k0][n],W[k0+1][n]}, {W[k0+8][n],W[k0+9][n]} },
// k0 = kt*16+(lane&3)*2, n = nt*8+(lane>>2).
__global__ void prep_kernel(const float* __restrict__ W1, const float* __restrict__ W2) {
    int idx = blockIdx.x * blockDim.x + threadIdx.x;
    if (idx == 0) g_counter = 0u;
    const int total1 = KT1 * NT1 * 32;
    if (idx < total1) {
        int lane = idx & 31, tile = idx >> 5;
        int nt = tile % NT1, kt = tile / NT1;
        int k0 = kt * 16 + (lane & 3) * 2;
        int n  = nt * 8 + (lane >> 2);
        float w00 = W1[(size_t)k0 * HID + n];
        float w01 = W1[(size_t)(k0 + 1) * HID + n];
        float w10 = W1[(size_t)(k0 + 8) * HID + n];
        float w11 = W1[(size_t)(k0 + 9) * HID + n];
        size_t dst = (size_t)2 * (((size_t)kt * 8 + (nt >> 1)) * 32 + lane) + (nt & 1);
        g_w1[dst] = make_uint2(pack2h(w00, w01), pack2h(w10, w11));
    } else if (idx < total1 + KT2 * 8 * 32) {
        int j = idx - total1;
        int lane = j & 31, tile = j >> 5;
        int nt = tile % 8, kt = tile / 8;
        int k0 = kt * 16 + (lane & 3) * 2;
        int n  = nt * 8 + (lane >> 2);
        float w00 = W2[(size_t)k0 * TGT + n];
        float w01 = W2[(size_t)(k0 + 1) * TGT + n];
        float w10 = W2[(size_t)(k0 + 8) * TGT + n];
        float w11 = W2[(size_t)(k0 + 9) * TGT + n];
        size_t dst = (size_t)2 * (((size_t)kt * 4 + (nt >> 1)) * 32 + lane) + (nt & 1);
        g_w2[dst] = make_uint2(pack2h(w00, w01), pack2h(w10, w11));
    }
}

// ===================== main fused kernel =====================
extern "C" __global__ void __launch_bounds__(THREADS, 1)
edge_mlp(const float* __restrict__ ek, const float* __restrict__ vrk,
         const float* __restrict__ vsk, const float* __restrict__ u,
         const int* __restrict__ batch,
         const float* __restrict__ b1, const float* __restrict__ b2,
         float* __restrict__ out, int ngroups) {
    extern __shared__ __align__(16) unsigned char smem[];
    const int tid = threadIdx.x;

    // -------- prologue: weight fragments + biases to smem --------
    {
        uint4* d = (uint4*)(smem + S_W1);
        const uint4* s = (const uint4*)g_w1;
        for (int i = tid; i < 98304 / 16; i += THREADS) d[i] = s[i];
        d = (uint4*)(smem + S_W2); s = (const uint4*)g_w2;
        for (int i = tid; i < 16384 / 16; i += THREADS) d[i] = s[i];
        float* b1s = (float*)(smem + S_B1);
        float* b2s = (float*)(smem + S_B2);
        if (tid < HID) b1s[tid] = b1[tid];
        if (tid < TGT) b2s[tid] = b2[tid];
    }
    __syncthreads();

    const uint4* w1p = (const uint4*)(smem + S_W1);
    const uint4* w2p = (const uint4*)(smem + S_W2);
    const float* b1s = (const float*)(smem + S_B1);
    const float* b2s = (const float*)(smem + S_B2);

    const int lane = tid & 31;
    const int wid  = tid >> 5;
    const int qrow = lane >> 2;        // 0..7
    const int qcol = (lane & 3) * 2;   // 0,2,4,6

    uint4* hbuf = (uint4*)(smem + S_H + (size_t)wid * 8192u);

    unsigned int cur = 0xFFFFFFFFu;
    if (lane == 0) cur = atomicAdd(&g_counter, 1u);
    cur = __shfl_sync(0xFFFFFFFFu, cur, 0);

    while (cur < (unsigned)ngroups) {
        unsigned int nxt = 0xFFFFFFFFu;
        if (lane == 0) nxt = atomicAdd(&g_counter, 1u);

        const int rbase = (int)cur * 32;
        const int r00 = rbase + qrow,      r01 = r00 + 8;
        const int r10 = rbase + 16 + qrow, r11 = r10 + 8;
        const int g00 = batch[r00], g01 = batch[r01];
        const int g10 = batch[r10], g11 = batch[r11];

        // ============ GEMM1 in two N-phases (hidden cols ph*64..ph*64+63) ============
        #pragma unroll 1
        for (int ph = 0; ph < 2; ++ph) {
            const int ph4 = ph * 4;
            float acc[64];   // [rb(2)][ntlocal(8)][4]
            #pragma unroll
            for (int i = 0; i < 64; ++i) acc[i] = 0.f;

            float2 v[8];
            uint32_t af[8];
            const float *p0 = ek + (size_t)r00 * NEF + qcol;
            const float *p1 = ek + (size_t)r01 * NEF + qcol;
            const float *p2 = ek + (size_t)r10 * NEF + qcol;
            const float *p3 = ek + (size_t)r11 * NEF + qcol;
            load8(v, p0, p1, p2, p3);

            // rolled kt loop: small body, I$-friendly; cvt->load(kt+1)->MMA pipeline
            #pragma unroll 1
            for (int kt = 0; kt < KT1; ++kt) {
                cvt8(af, v);
                if (kt < KT1 - 1) {
                    if (kt == 3) {
                        p0 = vrk + (size_t)r00 * NNF + qcol;
                        p1 = vrk + (size_t)r01 * NNF + qcol;
                        p2 = vrk + (size_t)r10 * NNF + qcol;
                        p3 = vrk + (size_t)r11 * NNF + qcol;
                    } else if (kt == 11) {
                        p0 = vsk + (size_t)r00 * NNF + qcol;
                        p1 = vsk + (size_t)r01 * NNF + qcol;
                        p2 = vsk + (size_t)r10 * NNF + qcol;
                        p3 = vsk + (size_t)r11 * NNF + qcol;
                    } else if (kt == 19) {
                        p0 = u + (size_t)g00 * NGF + qcol;
                        p1 = u + (size_t)g01 * NGF + qcol;
                        p2 = u + (size_t)g10 * NGF + qcol;
                        p3 = u + (size_t)g11 * NGF + qcol;
                    } else {
                        p0 += 16; p1 += 16; p2 += 16; p3 += 16;
                    }
                    load8(v, p0, p1, p2, p3);
                }
                const uint4* bw = w1p + ((size_t)kt * 8 + ph4) * 32 + lane;
                #pragma unroll
                for (int np = 0; np < 4; ++np) {
                    const uint4 f = bw[np * 32];
                    mma_f16(acc + (np * 2) * 4,          af,     f.x, f.y);
                    mma_f16(acc + 32 + (np * 2) * 4,     af + 4, f.x, f.y);
                    mma_f16(acc + (np * 2 + 1) * 4,      af,     f.z, f.w);
                    mma_f16(acc + 32 + (np * 2 + 1) * 4, af + 4, f.z, f.w);
                }
            }

            // ---- bias + ReLU ----
            #pragma unroll
            for (int nt = 0; nt < 8; ++nt) {
                const float2 bb = *(const float2*)(b1s + ph * 64 + nt * 8 + qcol);
                #pragma unroll
                for (int rb = 0; rb < 2; ++rb) {
                    float* a = acc + rb * 32 + nt * 4;
                    a[0] = fmaxf(a[0] + bb.x, 0.f);
                    a[1] = fmaxf(a[1] + bb.y, 0.f);
                    a[2] = fmaxf(a[2] + bb.x, 0.f);
                    a[3] = fmaxf(a[3] + bb.y, 0.f);
                }
            }
            // ---- pack + spill h to per-warp smem (A-frag layout for GEMM2) ----
            #pragma unroll
            for (int j = 0; j < 4; ++j) {
                const int kk = ph4 + j;
                #pragma unroll
                for (int rb = 0; rb < 2; ++rb) {
                    const float* s = acc + rb * 32 + j * 8;
                    uint4 q;
                    q.x = pack2h(s[0], s[1]);
                    q.y = pack2h(s[2], s[3]);
                    q.z = pack2h(s[4], s[5]);
                    q.w = pack2h(s[6], s[7]);
                    hbuf[(kk * 2 + rb) * 32 + lane] = q;
                }
            }
        }

        // ================= GEMM2: h (smem) @ W2 =================
        float c2[64];
        #pragma unroll
        for (int i = 0; i < 64; ++i) c2[i] = 0.f;

        #pragma unroll 1
        for (int kk = 0; kk < KT2; ++kk) {
            uint4 A0 = hbuf[(kk * 2 + 0) * 32 + lane];
            uint4 A1 = hbuf[(kk * 2 + 1) * 32 + lane];
            const uint32_t* a0 = (const uint32_t*)&A0;
            const uint32_t* a1 = (const uint32_t*)&A1;
            const uint4* bw = w2p + (size_t)kk * 4 * 32 + lane;
            #pragma unroll
            for (int np = 0; np < 4; ++np) {
                const uint4 f = bw[np * 32];
                mma_f16(c2 + (np * 2) * 4,          a0, f.x, f.y);
                mma_f16(c2 + 32 + (np * 2) * 4,     a1, f.x, f.y);
                mma_f16(c2 + (np * 2 + 1) * 4,      a0, f.z, f.w);
                mma_f16(c2 + 32 + (np * 2 + 1) * 4, a1, f.z, f.w);
            }
        }

        // ================= epilogue: + b2, store fp32 =================
        #pragma unroll
        for (int nt = 0; nt < 8; ++nt) {
            const float2 bb = *(const float2*)(b2s + nt * 8 + qcol);
            {
                const float* c = c2 + nt * 4;
                float2 o0, o1;
                o0.x = c[0] + bb.x; o0.y = c[1] + bb.y;
                o1.x = c[2] + bb.x; o1.y = c[3] + bb.y;
                *(float2*)(out + (size_t)r00 * TGT + nt * 8 + qcol) = o0;
                *(float2*)(out + (size_t)r01 * TGT + nt * 8 + qcol) = o1;
            }
            {
                const float* c = c2 + 32 + nt * 4;
                float2 o0, o1;
                o0.x = c[0] + bb.x; o0.y = c[1] + bb.y;
                o1.x = c[2] + bb.x; o1.y = c[3] + bb.y;
                *(float2*)(out + (size_t)r10 * TGT + nt * 8 + qcol) = o0;
                *(float2*)(out + (size_t)r11 * TGT + nt * 8 + qcol) = o1;
            }
        }

        cur = __shfl_sync(0xFFFFFFFFu, nxt, 0);
    }
}

// ===================== launch =====================
extern "C" void kernel_launch(void* const* d_in, const int* in_sizes, int n_in,
                              void* d_out, int out_size) {
    (void)n_in; (void)out_size;
    const float* ek  = (const float*)d_in[0];
    const float* vrk = (const float*)d_in[1];
    const float* vsk = (const float*)d_in[2];
    const float* u   = (const float*)d_in[3];
    const int*   batch = (const int*)d_in[4];
    const float* W1  = (const float*)d_in[5];
    const float* b1  = (const float*)d_in[6];
    const float* W2  = (const float*)d_in[7];
    const float* b2  = (const float*)d_in[8];
    float* out = (float*)d_out;

    const int E = in_sizes[0] / NEF;
    const int ngroups = E / 32;

    const int prep_total = KT1 * NT1 * 32 + KT2 * 8 * 32;
    prep_kernel<<<(prep_total + 255) / 256, 256>>>(W1, W2);

    cudaFuncSetAttribute(edge_mlp, cudaFuncAttributeMaxDynamicSharedMemorySize, S_TOTAL);
    edge_mlp<<<GRID_X, THREADS, S_TOTAL>>>(ek, vrk, vsk, u, batch, b1, b2, out, ngroups);
}

// round 11
// speedup vs baseline: 1.2688x; 1.0677x over previous
#include <cuda_runtime.h>
#include <cuda_fp16.h>
#include <cstdint>

// ===================== problem constants =====================
#define NNF 128
#define NEF 64
#define NGF 64
#define HID 128
#define TGT 64

#define THREADS 512
#define NWARPS  16
#define GRID_X  152

#define KT1 24   // 384/16 k-tiles, GEMM1
#define NT1 16   // 128/8  n-tiles, GEMM1 (8 per phase)
#define KT2 8    // 128/16 k-tiles, GEMM2

// ===================== smem offsets (bytes) =====================
#define S_W1  0u        // 24 kt x 8 pairs x 32 lanes x 16B = 98304
#define S_W2  98304u    // 8 kt x 4 pairs x 32 x 16B = 16384
#define S_B1  114688u   // 512
#define S_B2  115200u   // 256
#define S_H   115456u   // 16 warps x 4096 (phase-0 h only)
#define S_TOTAL (S_H + NWARPS * 4096u)   // 180992

// ===================== helpers =====================
__device__ __forceinline__ uint32_t pack2h(float lo, float hi) {
    uint32_t r;
    asm("cvt.rn.f16x2.f32 %0, %1, %2;" : "=r"(r) : "f"(hi), "f"(lo));
    return r;
}
// D += A * B  (m16n8k16, fp16 in, f32 accum)
__device__ __forceinline__ void mma_f16(float* c, const uint32_t* a, uint32_t b0, uint32_t b1) {
    asm volatile("mma.sync.aligned.m16n8k16.row.col.f32.f16.f16.f32 "
        "{%0,%1,%2,%3}, {%4,%5,%6,%7}, {%8,%9}, {%0,%1,%2,%3};"
        : "+f"(c[0]), "+f"(c[1]), "+f"(c[2]), "+f"(c[3])
        : "r"(a[0]), "r"(a[1]), "r"(a[2]), "r"(a[3]), "r"(b0), "r"(b1));
}
__device__ __forceinline__ void load8(float2* v, const float* p0, const float* p1,
                                      const float* p2, const float* p3) {
    v[0] = *(const float2*)p0; v[1] = *(const float2*)(p0 + 8);
    v[2] = *(const float2*)p1; v[3] = *(const float2*)(p1 + 8);
    v[4] = *(const float2*)p2; v[5] = *(const float2*)(p2 + 8);
    v[6] = *(const float2*)p3; v[7] = *(const float2*)(p3 + 8);
}
__device__ __forceinline__ void cvt8(uint32_t* af, const float2* v) {
    af[0] = pack2h(v[0].x, v[0].y);  // (r00, c0)
    af[1] = pack2h(v[2].x, v[2].y);  // (r01, c0)
    af[2] = pack2h(v[1].x, v[1].y);  // (r00, c0+8)
    af[3] = pack2h(v[3].x, v[3].y);  // (r01, c0+8)
    af[4] = pack2h(v[4].x, v[4].y);  // (r10, c0)
    af[5] = pack2h(v[6].x, v[6].y);  // (r11, c0)
    af[6] = pack2h(v[5].x, v[5].y);  // (r10, c0+8)
    af[7] = pack2h(v[7].x, v[7].y);  // (r11, c0+8)
}

// ===================== device scratch (pair-interleaved fragments) =====================
__device__ __align__(16) uint2 g_w1[KT1 * NT1 * 32];
__device__ __align__(16) uint2 g_w2[KT2 * 8 * 32];
__device__ unsigned int g_counter;

// W1 [384,128], W2 [128,64] ([k][n] row-major) -> per-lane m16n8k16 B fragments,
// paired: uint4 entry ((kt*8+np)*32+lane) = {frag(nt=2np), frag(nt=2np+1)}.
// frag(kt,nt,lane) = { {W[k0][n],W[k0+1][n]}, {W[k0+8][n],W[k0+9][n]} },
// k0 = kt*16+(lane&3)*2, n = nt*8+(lane>>2).
__global__ void prep_kernel(const float* __restrict__ W1, const float* __restrict__ W2) {
    int idx = blockIdx.x * blockDim.x + threadIdx.x;
    if (idx == 0) g_counter = 0u;
    const int total1 = KT1 * NT1 * 32;
    if (idx < total1) {
        int lane = idx & 31, tile = idx >> 5;
        int nt = tile % NT1, kt = tile / NT1;
        int k0 = kt * 16 + (lane & 3) * 2;
        int n  = nt * 8 + (lane >> 2);
        float w00 = W1[(size_t)k0 * HID + n];
        float w01 = W1[(size_t)(k0 + 1) * HID + n];
        float w10 = W1[(size_t)(k0 + 8) * HID + n];
        float w11 = W1[(size_t)(k0 + 9) * HID + n];
        size_t dst = (size_t)2 * (((size_t)kt * 8 + (nt >> 1)) * 32 + lane) + (nt & 1);
        g_w1[dst] = make_uint2(pack2h(w00, w01), pack2h(w10, w11));
    } else if (idx < total1 + KT2 * 8 * 32) {
        int j = idx - total1;
        int lane = j & 31, tile = j >> 5;
        int nt = tile % 8, kt = tile / 8;
        int k0 = kt * 16 + (lane & 3) * 2;
        int n  = nt * 8 + (lane >> 2);
        float w00 = W2[(size_t)k0 * TGT + n];
        float w01 = W2[(size_t)(k0 + 1) * TGT + n];
        float w10 = W2[(size_t)(k0 + 8) * TGT + n];
        float w11 = W2[(size_t)(k0 + 9) * TGT + n];
        size_t dst = (size_t)2 * (((size_t)kt * 4 + (nt >> 1)) * 32 + lane) + (nt & 1);
        g_w2[dst] = make_uint2(pack2h(w00, w01), pack2h(w10, w11));
    }
}

// ===================== main fused kernel =====================
extern "C" __global__ void __launch_bounds__(THREADS, 1)
edge_mlp(const float* __restrict__ ek, const float* __restrict__ vrk,
         const float* __restrict__ vsk, const float* __restrict__ u,
         const int* __restrict__ batch,
         const float* __restrict__ b1, const float* __restrict__ b2,
         float* __restrict__ out, int ngroups) {
    extern __shared__ __align__(16) unsigned char smem[];
    const int tid = threadIdx.x;

    // -------- prologue: weight fragments + biases to smem --------
    {
        uint4* d = (uint4*)(smem + S_W1);
        const uint4* s = (const uint4*)g_w1;
        for (int i = tid; i < 98304 / 16; i += THREADS) d[i] = s[i];
        d = (uint4*)(smem + S_W2); s = (const uint4*)g_w2;
        for (int i = tid; i < 16384 / 16; i += THREADS) d[i] = s[i];
        float* b1s = (float*)(smem + S_B1);
        float* b2s = (float*)(smem + S_B2);
        if (tid < HID) b1s[tid] = b1[tid];
        if (tid < TGT) b2s[tid] = b2[tid];
    }
    __syncthreads();

    const uint4* w1p = (const uint4*)(smem + S_W1);
    const uint4* w2p = (const uint4*)(smem + S_W2);
    const float* b1s = (const float*)(smem + S_B1);
    const float* b2s = (const float*)(smem + S_B2);

    const int lane = tid & 31;
    const int wid  = tid >> 5;
    const int qrow = lane >> 2;        // 0..7
    const int qcol = (lane & 3) * 2;   // 0,2,4,6

    uint4* hbuf = (uint4*)(smem + S_H + (size_t)wid * 4096u);   // phase-0 h only

    unsigned int cur = 0xFFFFFFFFu;
    if (lane == 0) cur = atomicAdd(&g_counter, 1u);
    cur = __shfl_sync(0xFFFFFFFFu, cur, 0);

    while (cur < (unsigned)ngroups) {
        unsigned int nxt = 0xFFFFFFFFu;
        if (lane == 0) nxt = atomicAdd(&g_counter, 1u);

        const int rbase = (int)cur * 32;
        const int r00 = rbase + qrow,      r01 = r00 + 8;
        const int r10 = rbase + 16 + qrow, r11 = r10 + 8;
        const int g00 = batch[r00], g01 = batch[r01];
        const int g10 = batch[r10], g11 = batch[r11];

        uint32_t hpk[32];   // phase-1 h, packed fp16x2 (written in ph==1 only)

        // ============ GEMM1 in two N-phases (hidden cols ph*64..ph*64+63) ============
        #pragma unroll
        for (int ph = 0; ph < 2; ++ph) {
            const int ph4 = ph * 4;
            float acc[64];   // [rb(2)][ntlocal(8)][4]
            #pragma unroll
            for (int i = 0; i < 64; ++i) acc[i] = 0.f;

            float2 v[8];
            uint32_t af[8];
            const float *p0 = ek + (size_t)r00 * NEF + qcol;
            const float *p1 = ek + (size_t)r01 * NEF + qcol;
            const float *p2 = ek + (size_t)r10 * NEF + qcol;
            const float *p3 = ek + (size_t)r11 * NEF + qcol;
            load8(v, p0, p1, p2, p3);

            // rolled kt loop: cvt(current) -> load(kt+1) -> 16 MMAs
            #pragma unroll 1
            for (int kt = 0; kt < KT1; ++kt) {
                cvt8(af, v);
                if (kt < KT1 - 1) {
                    if (kt == 3) {
                        p0 = vrk + (size_t)r00 * NNF + qcol;
                        p1 = vrk + (size_t)r01 * NNF + qcol;
                        p2 = vrk + (size_t)r10 * NNF + qcol;
                        p3 = vrk + (size_t)r11 * NNF + qcol;
                    } else if (kt == 11) {
                        p0 = vsk + (size_t)r00 * NNF + qcol;
                        p1 = vsk + (size_t)r01 * NNF + qcol;
                        p2 = vsk + (size_t)r10 * NNF + qcol;
                        p3 = vsk + (size_t)r11 * NNF + qcol;
                    } else if (kt == 19) {
                        p0 = u + (size_t)g00 * NGF + qcol;
                        p1 = u + (size_t)g01 * NGF + qcol;
                        p2 = u + (size_t)g10 * NGF + qcol;
                        p3 = u + (size_t)g11 * NGF + qcol;
                    } else {
                        p0 += 16; p1 += 16; p2 += 16; p3 += 16;
                    }
                    load8(v, p0, p1, p2, p3);
                }
                const uint4* bw = w1p + ((size_t)kt * 8 + ph4) * 32 + lane;
                #pragma unroll
                for (int np = 0; np < 4; ++np) {
                    const uint4 f = bw[np * 32];
                    mma_f16(acc + (np * 2) * 4,          af,     f.x, f.y);
                    mma_f16(acc + 32 + (np * 2) * 4,     af + 4, f.x, f.y);
                    mma_f16(acc + (np * 2 + 1) * 4,      af,     f.z, f.w);
                    mma_f16(acc + 32 + (np * 2 + 1) * 4, af + 4, f.z, f.w);
                }
            }

            // ---- bias + ReLU ----
            #pragma unroll
            for (int nt = 0; nt < 8; ++nt) {
                const float2 bb = *(const float2*)(b1s + ph * 64 + nt * 8 + qcol);
                #pragma unroll
                for (int rb = 0; rb < 2; ++rb) {
                    float* a = acc + rb * 32 + nt * 4;
                    a[0] = fmaxf(a[0] + bb.x, 0.f);
                    a[1] = fmaxf(a[1] + bb.y, 0.f);
                    a[2] = fmaxf(a[2] + bb.x, 0.f);
                    a[3] = fmaxf(a[3] + bb.y, 0.f);
                }
            }
            // ---- pack h: phase 0 -> smem (4KB/warp), phase 1 -> registers ----
            #pragma unroll
            for (int j = 0; j < 4; ++j) {
                #pragma unroll
                for (int rb = 0; rb < 2; ++rb) {
                    const float* s = acc + rb * 32 + j * 8;
                    uint4 q;
                    q.x = pack2h(s[0], s[1]);
                    q.y = pack2h(s[2], s[3]);
                    q.z = pack2h(s[4], s[5]);
                    q.w = pack2h(s[6], s[7]);
                    if (ph == 0) {
                        hbuf[(j * 2 + rb) * 32 + lane] = q;
                    } else {
                        uint32_t* hp = hpk + j * 8 + rb * 4;
                        hp[0] = q.x; hp[1] = q.y; hp[2] = q.z; hp[3] = q.w;
                    }
                }
            }
        }

        // ================= GEMM2: h @ W2 (kk 0-3 from smem, 4-7 from regs) =================
        float c2[64];
        #pragma unroll
        for (int i = 0; i < 64; ++i) c2[i] = 0.f;

        #pragma unroll
        for (int kk = 0; kk < KT2; ++kk) {
            uint4 A0, A1;
            if (kk < 4) {
                A0 = hbuf[(kk * 2 + 0) * 32 + lane];
                A1 = hbuf[(kk * 2 + 1) * 32 + lane];
            } else {
                const uint32_t* h0 = hpk + (kk - 4) * 8;
                A0 = make_uint4(h0[0], h0[1], h0[2], h0[3]);
                A1 = make_uint4(h0[4], h0[5], h0[6], h0[7]);
            }
            const uint32_t* a0 = (const uint32_t*)&A0;
            const uint32_t* a1 = (const uint32_t*)&A1;
            const uint4* bw = w2p + (size_t)kk * 4 * 32 + lane;
            #pragma unroll
            for (int np = 0; np < 4; ++np) {
                const uint4 f = bw[np * 32];
                mma_f16(c2 + (np * 2) * 4,          a0, f.x, f.y);
                mma_f16(c2 + 32 + (np * 2) * 4,     a1, f.x, f.y);
                mma_f16(c2 + (np * 2 + 1) * 4,      a0, f.z, f.w);
                mma_f16(c2 + 32 + (np * 2 + 1) * 4, a1, f.z, f.w);
            }
        }

        // ================= epilogue: + b2, store fp32 =================
        #pragma unroll
        for (int nt = 0; nt < 8; ++nt) {
            const float2 bb = *(const float2*)(b2s + nt * 8 + qcol);
            {
                const float* c = c2 + nt * 4;
                float2 o0, o1;
                o0.x = c[0] + bb.x; o0.y = c[1] + bb.y;
                o1.x = c[2] + bb.x; o1.y = c[3] + bb.y;
                *(float2*)(out + (size_t)r00 * TGT + nt * 8 + qcol) = o0;
                *(float2*)(out + (size_t)r01 * TGT + nt * 8 + qcol) = o1;
            }
            {
                const float* c = c2 + 32 + nt * 4;
                float2 o0, o1;
                o0.x = c[0] + bb.x; o0.y = c[1] + bb.y;
                o1.x = c[2] + bb.x; o1.y = c[3] + bb.y;
                *(float2*)(out + (size_t)r10 * TGT + nt * 8 + qcol) = o0;
                *(float2*)(out + (size_t)r11 * TGT + nt * 8 + qcol) = o1;
            }
        }

        cur = __shfl_sync(0xFFFFFFFFu, nxt, 0);
    }
}

// ===================== launch =====================
extern "C" void kernel_launch(void* const* d_in, const int* in_sizes, int n_in,
                              void* d_out, int out_size) {
    (void)n_in; (void)out_size;
    const float* ek  = (const float*)d_in[0];
    const float* vrk = (const float*)d_in[1];
    const float* vsk = (const float*)d_in[2];
    const float* u   = (const float*)d_in[3];
    const int*   batch = (const int*)d_in[4];
    const float* W1  = (const float*)d_in[5];
    const float* b1  = (const float*)d_in[6];
    const float* W2  = (const float*)d_in[7];
    const float* b2  = (const float*)d_in[8];
    float* out = (float*)d_out;

    const int E = in_sizes[0] / NEF;
    const int ngroups = E / 32;

    const int prep_total = KT1 * NT1 * 32 + KT2 * 8 * 32;
    prep_kernel<<<(prep_total + 255) / 256, 256>>>(W1, W2);

    cudaFuncSetAttribute(edge_mlp, cudaFuncAttributeMaxDynamicSharedMemorySize, S_TOTAL);
    edge_mlp<<<GRID_X, THREADS, S_TOTAL>>>(ek, vrk, vsk, u, batch, b1, b2, out, ngroups);
}